// round 14
// baseline (speedup 1.0000x reference)
#include <cuda_runtime.h>
#include <cuda_bf16.h>

#define NN 50000
#define EE 600000
#define HH 128
#define LL 4
#define GG 256
#define CC 10
#define BNEPS 1e-5f
#define NBLK 196   // ceil(NN/256)

// ---------------- scratch (static device globals; no allocation) -------------
__device__ float g_agg[(size_t)NN * HH];
__device__ float g_z1[(size_t)NN * HH];
__device__ float g_z2[(size_t)NN * HH];
__device__ float g_pooled[GG * LL * HH];
__device__ float g_stats[LL * 2 * 2 * HH];   // [layer][stage][sum|sumsq][H]
__device__ int   g_deg[NN];
__device__ int   g_rowptr[NN];
__device__ int   g_cursor[NN];
__device__ int   g_srclist[EE];
__device__ int   g_bsum[256];
__device__ int   g_boff[256];
// pre-split weights, transposed: [stage*LL+layer][n][k], bf16 hi/lo
__device__ __nv_bfloat16 g_whi[2 * LL * HH * HH];
__device__ __nv_bfloat16 g_wlo[2 * LL * HH * HH];

__device__ __forceinline__ void red_add_v4(float* p, float4 v) {
    asm volatile("red.global.add.v4.f32 [%0], {%1,%2,%3,%4};"
                 :: "l"(p), "f"(v.x), "f"(v.y), "f"(v.z), "f"(v.w) : "memory");
}

__device__ __forceinline__ void mma_bf16(float* d, const unsigned* a,
                                         unsigned b0, unsigned b1) {
    asm volatile(
        "mma.sync.aligned.m16n8k16.row.col.f32.bf16.bf16.f32 "
        "{%0,%1,%2,%3},{%4,%5,%6,%7},{%8,%9},{%0,%1,%2,%3};\n"
        : "+f"(d[0]), "+f"(d[1]), "+f"(d[2]), "+f"(d[3])
        : "r"(a[0]), "r"(a[1]), "r"(a[2]), "r"(a[3]), "r"(b0), "r"(b1));
}

// ---------------- weight pre-split: W[k][n] fp32 -> [n][k] bf16 hi/lo --------
__global__ void wsplit_kernel(const float* __restrict__ W1,
                              const float* __restrict__ W2) {
    const int bid = blockIdx.x;               // 0..7: stage = bid>>2, layer = bid&3
    const float* W = ((bid >> 2) ? W2 : W1) + (bid & 3) * HH * HH;
    __nv_bfloat16* whi = g_whi + bid * HH * HH;
    __nv_bfloat16* wlo = g_wlo + bid * HH * HH;
    for (int i = threadIdx.x; i < HH * HH; i += blockDim.x) {
        int k = i >> 7, n = i & 127;
        float f = __ldg(W + i);
        __nv_bfloat16 h = __float2bfloat16(f);
        whi[n * HH + k] = h;
        wlo[n * HH + k] = __float2bfloat16(f - __bfloat162float(h));
    }
}

// ---------------- zero pooled + stats + degree -------------------------------
__global__ void zero_kernel() {
    const int P = GG * LL * HH;
    const int S = LL * 2 * 2 * HH;
    const int tot = P + S + NN;
    for (int i = blockIdx.x * blockDim.x + threadIdx.x; i < tot;
         i += gridDim.x * blockDim.x) {
        if (i < P) g_pooled[i] = 0.f;
        else if (i < P + S) g_stats[i - P] = 0.f;
        else g_deg[i - P - S] = 0;
    }
}

// ---------------- CSR build (parallel 3-phase scan) --------------------------
__global__ void count_kernel(const int* __restrict__ ei) {
    int e = blockIdx.x * blockDim.x + threadIdx.x;
    if (e < EE) atomicAdd(&g_deg[__ldg(ei + EE + e)], 1);
}

__global__ void bsum_kernel() {
    __shared__ int ws[8];
    const int t = threadIdx.x;
    int i = blockIdx.x * 256 + t;
    int d = (i < NN) ? g_deg[i] : 0;
#pragma unroll
    for (int off = 16; off > 0; off >>= 1)
        d += __shfl_down_sync(0xffffffffu, d, off);
    if ((t & 31) == 0) ws[t >> 5] = d;
    __syncthreads();
    if (t < 8) {
        int v = ws[t];
#pragma unroll
        for (int off = 4; off > 0; off >>= 1)
            v += __shfl_down_sync(0xffu, v, off);
        if (t == 0) g_bsum[blockIdx.x] = v;
    }
}

__global__ void bscan_kernel() {
    __shared__ int s[256];
    const int t = threadIdx.x;
    int v = (t < NBLK) ? g_bsum[t] : 0;
    s[t] = v;
    __syncthreads();
#pragma unroll
    for (int off = 1; off < 256; off <<= 1) {
        int u = (t >= off) ? s[t - off] : 0;
        __syncthreads();
        s[t] += u;
        __syncthreads();
    }
    g_boff[t] = (t == 0) ? 0 : s[t - 1];
}

__global__ void rowptr_kernel() {
    __shared__ int ws[8];
    const int t = threadIdx.x;
    const int lane = t & 31, wid = t >> 5;
    int i = blockIdx.x * 256 + t;
    int d = (i < NN) ? g_deg[i] : 0;
    int inc = d;
#pragma unroll
    for (int off = 1; off < 32; off <<= 1) {
        int u = __shfl_up_sync(0xffffffffu, inc, off);
        if (lane >= off) inc += u;
    }
    if (lane == 31) ws[wid] = inc;
    __syncthreads();
    if (t < 8) {
        int v = ws[t];
        int acc = 0;
        for (int j = 0; j < 8; j++) {
            int vj = __shfl_sync(0xffu, v, j);
            if (j == t) ws[t] = acc;
            acc += vj;
        }
    }
    __syncthreads();
    int excl = inc - d + ws[wid] + g_boff[blockIdx.x];
    if (i < NN) {
        g_rowptr[i] = excl;
        g_cursor[i] = excl;
    }
}

__global__ void fill_kernel(const int* __restrict__ ei) {
    int e = blockIdx.x * blockDim.x + threadIdx.x;
    if (e < EE) {
        int d = __ldg(ei + EE + e);
        int pos = atomicAdd(&g_cursor[d], 1);
        g_srclist[pos] = __ldg(ei + e);
    }
}

// ---------------- aggregation (with fused BN of prev layer + pooling) --------
template <int FIRST>
__global__ void agg_kernel(const float* __restrict__ x,
                           const float* __restrict__ eps, int layer,
                           const int* __restrict__ batch,
                           const float* __restrict__ gamma,
                           const float* __restrict__ beta) {
    const float4* h4 = (const float4*)(FIRST ? x : g_z2);
    float4* a4 = (float4*)g_agg;
    const int lane = threadIdx.x & 31;
    int warp = (blockIdx.x * blockDim.x + threadIdx.x) >> 5;
    const int nw = (gridDim.x * blockDim.x) >> 5;
    const float e1 = 1.f + __ldg(eps + layer);

    float scv[4], shv[4];
    if (!FIRST) {
        const float* st = g_stats + ((layer - 1) * 2 + 1) * 2 * HH;
#pragma unroll
        for (int j = 0; j < 4; j++) {
            int c = lane * 4 + j;
            float mu  = st[c] * (1.f / NN);
            float var = st[HH + c] * (1.f / NN) - mu * mu;
            float r   = rsqrtf(var + BNEPS);
            scv[j] = r * __ldg(gamma + c);
            shv[j] = __ldg(beta + c) - mu * scv[j];
        }
    }

#define BNAP(v) do { if (!FIRST) { \
        (v).x = fmaxf(fmaf((v).x, scv[0], shv[0]), 0.f); \
        (v).y = fmaxf(fmaf((v).y, scv[1], shv[1]), 0.f); \
        (v).z = fmaxf(fmaf((v).z, scv[2], shv[2]), 0.f); \
        (v).w = fmaxf(fmaf((v).w, scv[3], shv[3]), 0.f); } } while (0)

    for (int n = warp; n < NN; n += nw) {
        const int base = g_rowptr[n];
        const int deg = g_deg[n];
        float4 h = h4[(size_t)n * 32 + lane];
        BNAP(h);
        if (!FIRST)
            red_add_v4(g_pooled + __ldg(batch + n) * (LL * HH)
                       + (layer - 1) * HH + lane * 4, h);
        float4 acc = make_float4(e1 * h.x, e1 * h.y, e1 * h.z, e1 * h.w);
        int i = 0;
        for (; i + 4 <= deg; i += 4) {
            int s0 = __ldg(g_srclist + base + i);
            int s1 = __ldg(g_srclist + base + i + 1);
            int s2 = __ldg(g_srclist + base + i + 2);
            int s3 = __ldg(g_srclist + base + i + 3);
            float4 v0 = h4[(size_t)s0 * 32 + lane];
            float4 v1 = h4[(size_t)s1 * 32 + lane];
            float4 v2 = h4[(size_t)s2 * 32 + lane];
            float4 v3 = h4[(size_t)s3 * 32 + lane];
            BNAP(v0); BNAP(v1); BNAP(v2); BNAP(v3);
            acc.x += v0.x + v1.x + v2.x + v3.x;
            acc.y += v0.y + v1.y + v2.y + v3.y;
            acc.z += v0.z + v1.z + v2.z + v3.z;
            acc.w += v0.w + v1.w + v2.w + v3.w;
        }
        for (; i < deg; i++) {
            int s = __ldg(g_srclist + base + i);
            float4 v = h4[(size_t)s * 32 + lane];
            BNAP(v);
            acc.x += v.x; acc.y += v.y; acc.z += v.z; acc.w += v.w;
        }
        a4[(size_t)n * 32 + lane] = acc;
    }
#undef BNAP
}

// ---------------- tensor-core GEMM v2 (bf16 split-3, PRMT-based split) -------
// Z = op(A) @ W + bias ; W pre-split in g_whi/g_wlo (transposed [n][k]).
// Block tile 64(M) x 128(N), K-chunk 32. 8 warps: 2(M) x 4(N), warp tile 32x32.
template <int BNRELU>
__global__ __launch_bounds__(256) void gemm_tc(
        int layer,
        const float* __restrict__ bias,
        const float* __restrict__ gamma,
        const float* __restrict__ beta) {
    __shared__ __nv_bfloat16 Ahi[64][40];
    __shared__ __nv_bfloat16 Alo[64][40];
    __shared__ __nv_bfloat16 Bhi[128][40];
    __shared__ __nv_bfloat16 Blo[128][40];
    __shared__ float scA[HH], shA[HH];

    const float* A = BNRELU ? g_z1 : g_agg;
    float*       Z = BNRELU ? g_z2 : g_z1;
    float* statsOut = g_stats + (layer * 2 + BNRELU) * 2 * HH;
    const __nv_bfloat16* Whi = g_whi + (BNRELU * LL + layer) * HH * HH;
    const __nv_bfloat16* Wlo = g_wlo + (BNRELU * LL + layer) * HH * HH;

    const int t = threadIdx.x;
    if (BNRELU) {
        const float* st = g_stats + (layer * 2) * 2 * HH;
        if (t < HH) {
            float mu  = st[t] * (1.f / NN);
            float var = st[HH + t] * (1.f / NN) - mu * mu;
            float r   = rsqrtf(var + BNEPS);
            float sc  = r * __ldg(gamma + t);
            scA[t] = sc;
            shA[t] = __ldg(beta + t) - mu * sc;
        }
        __syncthreads();
    }

    const int lane = t & 31, warp = t >> 5;
    const int wM = warp >> 2, wN = warp & 3;     // 2 x 4 warp grid
    const int m0 = blockIdx.x * 64;

    const float4* A4 = (const float4*)A;

    float acc[2][4][4];
#pragma unroll
    for (int mt = 0; mt < 2; mt++)
#pragma unroll
        for (int nt = 0; nt < 4; nt++)
#pragma unroll
            for (int r = 0; r < 4; r++) acc[mt][nt][r] = 0.f;

    for (int kc = 0; kc < 4; kc++) {
        const int k0 = kc * 32;
        // ---- A tile 64x32: fp32 -> bf16 hi/lo via PRMT/LOP3 (no F2FP) -------
#pragma unroll
        for (int i = 0; i < 2; i++) {
            int idx = t + i * 256;
            int row = idx >> 3, c4 = idx & 7;
            int m = m0 + row;
            float4 v = make_float4(0.f, 0.f, 0.f, 0.f);
            if (m < NN) {
                v = A4[(size_t)m * 32 + (k0 >> 2) + c4];
                if (BNRELU) {
                    int c = k0 + c4 * 4;
                    v.x = fmaxf(fmaf(v.x, scA[c + 0], shA[c + 0]), 0.f);
                    v.y = fmaxf(fmaf(v.y, scA[c + 1], shA[c + 1]), 0.f);
                    v.z = fmaxf(fmaf(v.z, scA[c + 2], shA[c + 2]), 0.f);
                    v.w = fmaxf(fmaf(v.w, scA[c + 3], shA[c + 3]), 0.f);
                }
            }
            unsigned u0 = __float_as_uint(v.x), u1 = __float_as_uint(v.y);
            unsigned u2 = __float_as_uint(v.z), u3 = __float_as_uint(v.w);
            unsigned hi01 = __byte_perm(u0, u1, 0x7632);
            unsigned hi23 = __byte_perm(u2, u3, 0x7632);
            float l0 = v.x - __uint_as_float(u0 & 0xFFFF0000u);
            float l1 = v.y - __uint_as_float(u1 & 0xFFFF0000u);
            float l2 = v.z - __uint_as_float(u2 & 0xFFFF0000u);
            float l3 = v.w - __uint_as_float(u3 & 0xFFFF0000u);
            unsigned lo01 = __byte_perm(__float_as_uint(l0), __float_as_uint(l1), 0x7632);
            unsigned lo23 = __byte_perm(__float_as_uint(l2), __float_as_uint(l3), 0x7632);
            *(unsigned*)&Ahi[row][c4 * 4]     = hi01;
            *(unsigned*)&Ahi[row][c4 * 4 + 2] = hi23;
            *(unsigned*)&Alo[row][c4 * 4]     = lo01;
            *(unsigned*)&Alo[row][c4 * 4 + 2] = lo23;
        }
        // ---- B tile: pure copy from pre-split transposed weights -------------
#pragma unroll
        for (int i = 0; i < 4; i++) {
            int idx = t + i * 256;            // 0..1023
            int n = idx >> 3, j = idx & 7;
            uint2 vh = *(const uint2*)(Whi + n * HH + k0 + j * 4);
            uint2 vl = *(const uint2*)(Wlo + n * HH + k0 + j * 4);
            *(uint2*)&Bhi[n][j * 4] = vh;
            *(uint2*)&Blo[n][j * 4] = vl;
        }
        __syncthreads();
        // ---- mma: D += Ahi*Bhi + Alo*Bhi + Ahi*Blo ---------------------------
#pragma unroll
        for (int ks = 0; ks < 2; ks++) {
            const int kk = ks * 16;
            unsigned ah[2][4], al[2][4];
#pragma unroll
            for (int mt = 0; mt < 2; mt++) {
                int ar = wM * 32 + mt * 16 + (lane >> 2);
                int ac = kk + (lane & 3) * 2;
                ah[mt][0] = *(const unsigned*)&Ahi[ar][ac];
                ah[mt][1] = *(const unsigned*)&Ahi[ar + 8][ac];
                ah[mt][2] = *(const unsigned*)&Ahi[ar][ac + 8];
                ah[mt][3] = *(const unsigned*)&Ahi[ar + 8][ac + 8];
                al[mt][0] = *(const unsigned*)&Alo[ar][ac];
                al[mt][1] = *(const unsigned*)&Alo[ar + 8][ac];
                al[mt][2] = *(const unsigned*)&Alo[ar][ac + 8];
                al[mt][3] = *(const unsigned*)&Alo[ar + 8][ac + 8];
            }
#pragma unroll
            for (int nt = 0; nt < 4; nt++) {
                int br = wN * 32 + nt * 8 + (lane >> 2);
                int bc = kk + (lane & 3) * 2;
                unsigned bh0 = *(const unsigned*)&Bhi[br][bc];
                unsigned bh1 = *(const unsigned*)&Bhi[br][bc + 8];
                unsigned bl0 = *(const unsigned*)&Blo[br][bc];
                unsigned bl1 = *(const unsigned*)&Blo[br][bc + 8];
#pragma unroll
                for (int mt = 0; mt < 2; mt++) {
                    mma_bf16(acc[mt][nt], ah[mt], bh0, bh1);
                    mma_bf16(acc[mt][nt], al[mt], bh0, bh1);
                    mma_bf16(acc[mt][nt], ah[mt], bl0, bl1);
                }
            }
        }
        __syncthreads();
    }

    // ---- epilogue: bias, store Z, BN stats (shuffle-reduced column sums) ----
    float2 colS[4], colQ[4];
#pragma unroll
    for (int nt = 0; nt < 4; nt++) {
        colS[nt] = make_float2(0.f, 0.f);
        colQ[nt] = make_float2(0.f, 0.f);
    }
#pragma unroll
    for (int mt = 0; mt < 2; mt++) {
#pragma unroll
        for (int nt = 0; nt < 4; nt++) {
            int col = wN * 32 + nt * 8 + (lane & 3) * 2;
            int r0 = m0 + wM * 32 + mt * 16 + (lane >> 2);
            int r1 = r0 + 8;
            float b0 = __ldg(bias + col), b1 = __ldg(bias + col + 1);
            float d0 = acc[mt][nt][0] + b0, d1 = acc[mt][nt][1] + b1;
            float d2 = acc[mt][nt][2] + b0, d3 = acc[mt][nt][3] + b1;
            if (r0 < NN) {
                *(float2*)&Z[(size_t)r0 * HH + col] = make_float2(d0, d1);
            } else { d0 = 0.f; d1 = 0.f; }
            if (r1 < NN) {
                *(float2*)&Z[(size_t)r1 * HH + col] = make_float2(d2, d3);
            } else { d2 = 0.f; d3 = 0.f; }
            colS[nt].x += d0 + d2;
            colS[nt].y += d1 + d3;
            colQ[nt].x += d0 * d0 + d2 * d2;
            colQ[nt].y += d1 * d1 + d3 * d3;
        }
    }
#pragma unroll
    for (int nt = 0; nt < 4; nt++) {
#pragma unroll
        for (int m = 4; m <= 16; m <<= 1) {
            colS[nt].x += __shfl_xor_sync(0xffffffffu, colS[nt].x, m);
            colS[nt].y += __shfl_xor_sync(0xffffffffu, colS[nt].y, m);
            colQ[nt].x += __shfl_xor_sync(0xffffffffu, colQ[nt].x, m);
            colQ[nt].y += __shfl_xor_sync(0xffffffffu, colQ[nt].y, m);
        }
    }
    if (lane < 4) {
#pragma unroll
        for (int nt = 0; nt < 4; nt++) {
            int col = wN * 32 + nt * 8 + lane * 2;
            atomicAdd(statsOut + col,          colS[nt].x);
            atomicAdd(statsOut + col + 1,      colS[nt].y);
            atomicAdd(statsOut + HH + col,     colQ[nt].x);
            atomicAdd(statsOut + HH + col + 1, colQ[nt].y);
        }
    }
}

// ---------------- final layer: BN(z2)+ReLU -> pool only ----------------------
__global__ void finalpool_kernel(int layer,
                                 const int* __restrict__ batch,
                                 const float* __restrict__ gamma,
                                 const float* __restrict__ beta) {
    const int q = threadIdx.x & 31;
    const int slot = threadIdx.x >> 5;
    const float* st = g_stats + (layer * 2 + 1) * 2 * HH;

    float scv[4], shv[4];
#pragma unroll
    for (int j = 0; j < 4; j++) {
        int c = q * 4 + j;
        float mu  = st[c] * (1.f / NN);
        float var = st[HH + c] * (1.f / NN) - mu * mu;
        float r   = rsqrtf(var + BNEPS);
        scv[j] = r * __ldg(gamma + c);
        shv[j] = __ldg(beta + c) - mu * scv[j];
    }

    for (int n = blockIdx.x * 8 + slot; n < NN; n += gridDim.x * 8) {
        float4 z = ((const float4*)(g_z2 + (size_t)n * HH))[q];
        float4 h;
        h.x = fmaxf(fmaf(z.x, scv[0], shv[0]), 0.f);
        h.y = fmaxf(fmaf(z.y, scv[1], shv[1]), 0.f);
        h.z = fmaxf(fmaf(z.z, scv[2], shv[2]), 0.f);
        h.w = fmaxf(fmaf(z.w, scv[3], shv[3]), 0.f);
        int b = __ldg(batch + n);
        red_add_v4(g_pooled + b * (LL * HH) + layer * HH + q * 4, h);
    }
}

// ---------------- head -------------------------------------------------------
__global__ void head_kernel(const float* __restrict__ fc1w,
                            const float* __restrict__ fc1b,
                            const float* __restrict__ fc2w,
                            const float* __restrict__ fc2b,
                            float* __restrict__ out) {
    __shared__ float p[LL * HH];
    __shared__ float tbuf[HH];
    const int g = blockIdx.x;
    const int j = threadIdx.x;
    for (int k = j; k < LL * HH; k += HH) p[k] = g_pooled[g * (LL * HH) + k];
    __syncthreads();
    float acc = __ldg(fc1b + j);
#pragma unroll 4
    for (int k = 0; k < LL * HH; k++) acc = fmaf(p[k], __ldg(fc1w + k * HH + j), acc);
    tbuf[j] = fmaxf(acc, 0.f);
    __syncthreads();
    if (j < CC) {
        float o = __ldg(fc2b + j);
#pragma unroll 4
        for (int k = 0; k < HH; k++) o = fmaf(tbuf[k], __ldg(fc2w + k * CC + j), o);
        out[g * CC + j] = o;
    }
}

// ---------------- launch -----------------------------------------------------
extern "C" void kernel_launch(void* const* d_in, const int* in_sizes, int n_in,
                              void* d_out, int out_size) {
    const float* x    = (const float*)d_in[0];
    const int*   ei   = (const int*)  d_in[1];
    const int*   batch= (const int*)  d_in[2];
    const float* W1   = (const float*)d_in[3];
    const float* b1   = (const float*)d_in[4];
    const float* g1   = (const float*)d_in[5];
    const float* bt1  = (const float*)d_in[6];
    const float* W2   = (const float*)d_in[7];
    const float* b2   = (const float*)d_in[8];
    const float* g2   = (const float*)d_in[9];
    const float* bt2  = (const float*)d_in[10];
    const float* eps  = (const float*)d_in[11];
    const float* fc1w = (const float*)d_in[12];
    const float* fc1b = (const float*)d_in[13];
    const float* fc2w = (const float*)d_in[14];
    const float* fc2b = (const float*)d_in[15];
    float* out = (float*)d_out;

    zero_kernel<<<180, 1024>>>();
    wsplit_kernel<<<8, 256>>>(W1, W2);
    count_kernel<<<(EE + 255) / 256, 256>>>(ei);
    bsum_kernel<<<NBLK, 256>>>();
    bscan_kernel<<<1, 256>>>();
    rowptr_kernel<<<NBLK, 256>>>();
    fill_kernel<<<(EE + 255) / 256, 256>>>(ei);

    const int gemmBlocks = (NN + 63) / 64;  // 782
    for (int i = 0; i < LL; i++) {
        if (i == 0)
            agg_kernel<1><<<2048, 256>>>(x, eps, 0, batch,
                                         (const float*)0, (const float*)0);
        else
            agg_kernel<0><<<2048, 256>>>(x, eps, i, batch,
                                         g2 + (i - 1) * HH, bt2 + (i - 1) * HH);
        gemm_tc<0><<<gemmBlocks, 256>>>(i, b1 + i * HH,
                                        (const float*)0, (const float*)0);
        gemm_tc<1><<<gemmBlocks, 256>>>(i, b2 + i * HH,
                                        g1 + i * HH, bt1 + i * HH);
    }
    finalpool_kernel<<<2048, 256>>>(LL - 1, batch,
                                    g2 + (LL - 1) * HH, bt2 + (LL - 1) * HH);
    head_kernel<<<GG, HH>>>(fc1w, fc1b, fc2w, fc2b, out);
}

// round 15
// speedup vs baseline: 1.1939x; 1.1939x over previous
#include <cuda_runtime.h>

#define NN 50000
#define EE 600000
#define HH 128
#define LL 4
#define GG 256
#define CC 10
#define BNEPS 1e-5f
#define NBLK 196   // ceil(NN/256)

// ---------------- scratch (static device globals; no allocation) -------------
__device__ float g_agg[(size_t)NN * HH];
__device__ float g_z1[(size_t)NN * HH];
__device__ float g_z2[(size_t)NN * HH];
__device__ float g_pooled[GG * LL * HH];
__device__ float g_stats[LL * 2 * 2 * HH];   // [layer][stage][sum|sumsq][H]
__device__ int   g_deg[NN];
__device__ int   g_rowptr[NN];
__device__ int   g_cursor[NN];
__device__ int   g_srclist[EE];
__device__ int   g_bsum[256];
__device__ int   g_boff[256];

__device__ __forceinline__ void red_add_v4(float* p, float4 v) {
    asm volatile("red.global.add.v4.f32 [%0], {%1,%2,%3,%4};"
                 :: "l"(p), "f"(v.x), "f"(v.y), "f"(v.z), "f"(v.w) : "memory");
}

// packed fp32x2 helpers (Blackwell; fma.rn.f32x2 only reachable via PTX)
__device__ __forceinline__ unsigned long long packf2(float lo, float hi) {
    unsigned long long r;
    asm("mov.b64 %0, {%1, %2};" : "=l"(r) : "r"(__float_as_uint(lo)), "r"(__float_as_uint(hi)));
    return r;
}
__device__ __forceinline__ unsigned long long packf2dup(float a) {
    unsigned long long r;
    asm("mov.b64 %0, {%1, %1};" : "=l"(r) : "r"(__float_as_uint(a)));
    return r;
}
__device__ __forceinline__ void fma2(unsigned long long& d,
                                     unsigned long long a, unsigned long long b) {
    asm("fma.rn.f32x2 %0, %1, %2, %0;" : "+l"(d) : "l"(a), "l"(b));
}

// ---------------- zero pooled + stats + degree -------------------------------
__global__ void zero_kernel() {
    const int P = GG * LL * HH;
    const int S = LL * 2 * 2 * HH;
    const int tot = P + S + NN;
    for (int i = blockIdx.x * blockDim.x + threadIdx.x; i < tot;
         i += gridDim.x * blockDim.x) {
        if (i < P) g_pooled[i] = 0.f;
        else if (i < P + S) g_stats[i - P] = 0.f;
        else g_deg[i - P - S] = 0;
    }
}

// ---------------- CSR build (parallel 3-phase scan) --------------------------
__global__ void count_kernel(const int* __restrict__ ei) {
    int e = blockIdx.x * blockDim.x + threadIdx.x;
    if (e < EE) atomicAdd(&g_deg[__ldg(ei + EE + e)], 1);
}

__global__ void bsum_kernel() {
    __shared__ int ws[8];
    const int t = threadIdx.x;
    int i = blockIdx.x * 256 + t;
    int d = (i < NN) ? g_deg[i] : 0;
#pragma unroll
    for (int off = 16; off > 0; off >>= 1)
        d += __shfl_down_sync(0xffffffffu, d, off);
    if ((t & 31) == 0) ws[t >> 5] = d;
    __syncthreads();
    if (t < 8) {
        int v = ws[t];
#pragma unroll
        for (int off = 4; off > 0; off >>= 1)
            v += __shfl_down_sync(0xffu, v, off);
        if (t == 0) g_bsum[blockIdx.x] = v;
    }
}

__global__ void bscan_kernel() {
    __shared__ int s[256];
    const int t = threadIdx.x;
    int v = (t < NBLK) ? g_bsum[t] : 0;
    s[t] = v;
    __syncthreads();
#pragma unroll
    for (int off = 1; off < 256; off <<= 1) {
        int u = (t >= off) ? s[t - off] : 0;
        __syncthreads();
        s[t] += u;
        __syncthreads();
    }
    g_boff[t] = (t == 0) ? 0 : s[t - 1];
}

__global__ void rowptr_kernel() {
    __shared__ int ws[8];
    const int t = threadIdx.x;
    const int lane = t & 31, wid = t >> 5;
    int i = blockIdx.x * 256 + t;
    int d = (i < NN) ? g_deg[i] : 0;
    int inc = d;
#pragma unroll
    for (int off = 1; off < 32; off <<= 1) {
        int u = __shfl_up_sync(0xffffffffu, inc, off);
        if (lane >= off) inc += u;
    }
    if (lane == 31) ws[wid] = inc;
    __syncthreads();
    if (t < 8) {
        int v = ws[t];
        int acc = 0;
        for (int j = 0; j < 8; j++) {
            int vj = __shfl_sync(0xffu, v, j);
            if (j == t) ws[t] = acc;
            acc += vj;
        }
    }
    __syncthreads();
    int excl = inc - d + ws[wid] + g_boff[blockIdx.x];
    if (i < NN) {
        g_rowptr[i] = excl;
        g_cursor[i] = excl;
    }
}

__global__ void fill_kernel(const int* __restrict__ ei) {
    int e = blockIdx.x * blockDim.x + threadIdx.x;
    if (e < EE) {
        int d = __ldg(ei + EE + e);
        int pos = atomicAdd(&g_cursor[d], 1);
        g_srclist[pos] = __ldg(ei + e);
    }
}

// ---------------- aggregation (with fused BN of prev layer + pooling) --------
template <int FIRST>
__global__ void agg_kernel(const float* __restrict__ x,
                           const float* __restrict__ eps, int layer,
                           const int* __restrict__ batch,
                           const float* __restrict__ gamma,
                           const float* __restrict__ beta) {
    const float4* h4 = (const float4*)(FIRST ? x : g_z2);
    float4* a4 = (float4*)g_agg;
    const int lane = threadIdx.x & 31;
    int warp = (blockIdx.x * blockDim.x + threadIdx.x) >> 5;
    const int nw = (gridDim.x * blockDim.x) >> 5;
    const float e1 = 1.f + __ldg(eps + layer);

    float scv[4], shv[4];
    if (!FIRST) {
        const float* st = g_stats + ((layer - 1) * 2 + 1) * 2 * HH;
#pragma unroll
        for (int j = 0; j < 4; j++) {
            int c = lane * 4 + j;
            float mu  = st[c] * (1.f / NN);
            float var = st[HH + c] * (1.f / NN) - mu * mu;
            float r   = rsqrtf(var + BNEPS);
            scv[j] = r * __ldg(gamma + c);
            shv[j] = __ldg(beta + c) - mu * scv[j];
        }
    }

#define BNAP(v) do { if (!FIRST) { \
        (v).x = fmaxf(fmaf((v).x, scv[0], shv[0]), 0.f); \
        (v).y = fmaxf(fmaf((v).y, scv[1], shv[1]), 0.f); \
        (v).z = fmaxf(fmaf((v).z, scv[2], shv[2]), 0.f); \
        (v).w = fmaxf(fmaf((v).w, scv[3], shv[3]), 0.f); } } while (0)

    for (int n = warp; n < NN; n += nw) {
        const int base = g_rowptr[n];
        const int deg = g_deg[n];
        float4 h = h4[(size_t)n * 32 + lane];
        BNAP(h);
        if (!FIRST)
            red_add_v4(g_pooled + __ldg(batch + n) * (LL * HH)
                       + (layer - 1) * HH + lane * 4, h);
        float4 acc = make_float4(e1 * h.x, e1 * h.y, e1 * h.z, e1 * h.w);
        int i = 0;
        for (; i + 4 <= deg; i += 4) {
            int s0 = __ldg(g_srclist + base + i);
            int s1 = __ldg(g_srclist + base + i + 1);
            int s2 = __ldg(g_srclist + base + i + 2);
            int s3 = __ldg(g_srclist + base + i + 3);
            float4 v0 = h4[(size_t)s0 * 32 + lane];
            float4 v1 = h4[(size_t)s1 * 32 + lane];
            float4 v2 = h4[(size_t)s2 * 32 + lane];
            float4 v3 = h4[(size_t)s3 * 32 + lane];
            BNAP(v0); BNAP(v1); BNAP(v2); BNAP(v3);
            acc.x += v0.x + v1.x + v2.x + v3.x;
            acc.y += v0.y + v1.y + v2.y + v3.y;
            acc.z += v0.z + v1.z + v2.z + v3.z;
            acc.w += v0.w + v1.w + v2.w + v3.w;
        }
        for (; i < deg; i++) {
            int s = __ldg(g_srclist + base + i);
            float4 v = h4[(size_t)s * 32 + lane];
            BNAP(v);
            acc.x += v.x; acc.y += v.y; acc.z += v.z; acc.w += v.w;
        }
        a4[(size_t)n * 32 + lane] = acc;
    }
#undef BNAP
}

// ---------------- GEMM (fp32, f32x2 packed FMA inner loop) -------------------
// Z = op(A) @ W + bias; epilogue: BN stats
// BNRELU=0: A = g_agg -> Z = g_z1, stats stage 0
// BNRELU=1: A = relu(BN(g_z1)) -> Z = g_z2, stats stage 1
template <int BNRELU>
__global__ __launch_bounds__(256, 2) void gemm_kernel(
        int layer,
        const float* __restrict__ W,
        const float* __restrict__ bias,
        const float* __restrict__ gamma,
        const float* __restrict__ beta) {
    __shared__ float  As[16][132];   // transposed A tile [k][m]
    __shared__ float4 Bs[16][32];    // B tile [k][c4]
    __shared__ float  red[16][128];  // stats reduction
    __shared__ float  scA[HH], shA[HH];

    const float* A = BNRELU ? g_z1 : g_agg;
    float*       Z = BNRELU ? g_z2 : g_z1;
    float* statsOut = g_stats + (layer * 2 + BNRELU) * 2 * HH;

    const int t = threadIdx.x;
    if (BNRELU) {
        const float* st = g_stats + (layer * 2) * 2 * HH;
        if (t < HH) {
            float mu  = st[t] * (1.f / NN);
            float var = st[HH + t] * (1.f / NN) - mu * mu;
            float r   = rsqrtf(var + BNEPS);
            float sc  = r * __ldg(gamma + t);
            scA[t] = sc;
            shA[t] = __ldg(beta + t) - mu * sc;
        }
        __syncthreads();
    }

    const int m0 = blockIdx.x * 128;
    const int tx = t & 15;          // col group: cols tx*4 and tx*4+64
    const int ty = t >> 4;          // row group: rows ty*4 and ty*4+64

    const float4* A4 = (const float4*)A;
    const float4* W4 = (const float4*)W;

    // accumulators: 8 rows x 8 cols as f32x2 pairs:
    // accA2[r][0..1] = cols (tx*4 .. tx*4+3); accB2[r][0..1] = cols +64
    unsigned long long accA2[8][2], accB2[8][2];
#pragma unroll
    for (int i = 0; i < 8; i++) {
        accA2[i][0] = 0ull; accA2[i][1] = 0ull;
        accB2[i][0] = 0ull; accB2[i][1] = 0ull;
    }

    for (int k0 = 0; k0 < HH; k0 += 16) {
        // A tile: 128 rows x 16 cols, stored transposed
#pragma unroll
        for (int j = 0; j < 2; j++) {
            int idx = t + j * 256;
            int row = idx >> 2, cq = idx & 3;
            int m = m0 + row;
            float4 v = make_float4(0.f, 0.f, 0.f, 0.f);
            if (m < NN) {
                v = A4[(size_t)m * 32 + (k0 >> 2) + cq];
                if (BNRELU) {
                    int c = k0 + cq * 4;
                    v.x = fmaxf(fmaf(v.x, scA[c + 0], shA[c + 0]), 0.f);
                    v.y = fmaxf(fmaf(v.y, scA[c + 1], shA[c + 1]), 0.f);
                    v.z = fmaxf(fmaf(v.z, scA[c + 2], shA[c + 2]), 0.f);
                    v.w = fmaxf(fmaf(v.w, scA[c + 3], shA[c + 3]), 0.f);
                }
            }
            As[cq * 4 + 0][row] = v.x;
            As[cq * 4 + 1][row] = v.y;
            As[cq * 4 + 2][row] = v.z;
            As[cq * 4 + 3][row] = v.w;
        }
        // B tile: 16 rows x 128 cols
#pragma unroll
        for (int j = 0; j < 2; j++) {
            int idx = t + j * 256;
            int kr = idx >> 5, c4 = idx & 31;
            Bs[kr][c4] = W4[(size_t)(k0 + kr) * 32 + c4];
        }
        __syncthreads();
#pragma unroll
        for (int k = 0; k < 16; k++) {
            float4 a0 = *(const float4*)&As[k][ty * 4];
            float4 a1 = *(const float4*)&As[k][ty * 4 + 64];
            float4 b0 = Bs[k][tx];
            float4 b1 = Bs[k][tx + 16];
            unsigned long long pb0 = packf2(b0.x, b0.y);
            unsigned long long pb1 = packf2(b0.z, b0.w);
            unsigned long long pb2 = packf2(b1.x, b1.y);
            unsigned long long pb3 = packf2(b1.z, b1.w);
            float ar[8] = {a0.x, a0.y, a0.z, a0.w, a1.x, a1.y, a1.z, a1.w};
#pragma unroll
            for (int r = 0; r < 8; r++) {
                unsigned long long pa = packf2dup(ar[r]);
                fma2(accA2[r][0], pa, pb0);
                fma2(accA2[r][1], pa, pb1);
                fma2(accB2[r][0], pa, pb2);
                fma2(accB2[r][1], pa, pb3);
            }
        }
        __syncthreads();
    }

    // epilogue: unpack, bias, store, per-thread column sums
    const float4 bb0 = __ldg(((const float4*)bias) + tx);
    const float4 bb1 = __ldg(((const float4*)bias) + tx + 16);
    float4 s0 = make_float4(0.f, 0.f, 0.f, 0.f), s1 = s0, q0 = s0, q1 = s0;
    float4* Z4 = (float4*)Z;
#pragma unroll
    for (int r = 0; r < 8; r++) {
        int m = m0 + ty * 4 + ((r < 4) ? r : 64 + (r - 4));
        if (m < NN) {
            uint2 uA0 = *(uint2*)&accA2[r][0];
            uint2 uA1 = *(uint2*)&accA2[r][1];
            uint2 uB0 = *(uint2*)&accB2[r][0];
            uint2 uB1 = *(uint2*)&accB2[r][1];
            float4 z0, z1;
            z0.x = __uint_as_float(uA0.x) + bb0.x;
            z0.y = __uint_as_float(uA0.y) + bb0.y;
            z0.z = __uint_as_float(uA1.x) + bb0.z;
            z0.w = __uint_as_float(uA1.y) + bb0.w;
            z1.x = __uint_as_float(uB0.x) + bb1.x;
            z1.y = __uint_as_float(uB0.y) + bb1.y;
            z1.z = __uint_as_float(uB1.x) + bb1.z;
            z1.w = __uint_as_float(uB1.y) + bb1.w;
            Z4[(size_t)m * 32 + tx] = z0;
            Z4[(size_t)m * 32 + tx + 16] = z1;
            s0.x += z0.x; s0.y += z0.y; s0.z += z0.z; s0.w += z0.w;
            s1.x += z1.x; s1.y += z1.y; s1.z += z1.z; s1.w += z1.w;
            q0.x = fmaf(z0.x, z0.x, q0.x); q0.y = fmaf(z0.y, z0.y, q0.y);
            q0.z = fmaf(z0.z, z0.z, q0.z); q0.w = fmaf(z0.w, z0.w, q0.w);
            q1.x = fmaf(z1.x, z1.x, q1.x); q1.y = fmaf(z1.y, z1.y, q1.y);
            q1.z = fmaf(z1.z, z1.z, q1.z); q1.w = fmaf(z1.w, z1.w, q1.w);
        }
    }
    // block-reduce stats in smem -> 256 atomics per block
    *(float4*)&red[ty][tx * 4]      = s0;
    *(float4*)&red[ty][tx * 4 + 64] = s1;
    __syncthreads();
    if (t < 128) {
        float v = 0.f;
#pragma unroll
        for (int j = 0; j < 16; j++) v += red[j][t];
        atomicAdd(statsOut + t, v);
    }
    __syncthreads();
    *(float4*)&red[ty][tx * 4]      = q0;
    *(float4*)&red[ty][tx * 4 + 64] = q1;
    __syncthreads();
    if (t < 128) {
        float v = 0.f;
#pragma unroll
        for (int j = 0; j < 16; j++) v += red[j][t];
        atomicAdd(statsOut + HH + t, v);
    }
}

// ---------------- final layer: BN(z2)+ReLU -> pool only ----------------------
__global__ void finalpool_kernel(int layer,
                                 const int* __restrict__ batch,
                                 const float* __restrict__ gamma,
                                 const float* __restrict__ beta) {
    const int q = threadIdx.x & 31;
    const int slot = threadIdx.x >> 5;
    const float* st = g_stats + (layer * 2 + 1) * 2 * HH;

    float scv[4], shv[4];
#pragma unroll
    for (int j = 0; j < 4; j++) {
        int c = q * 4 + j;
        float mu  = st[c] * (1.f / NN);
        float var = st[HH + c] * (1.f / NN) - mu * mu;
        float r   = rsqrtf(var + BNEPS);
        scv[j] = r * __ldg(gamma + c);
        shv[j] = __ldg(beta + c) - mu * scv[j];
    }

    for (int n = blockIdx.x * 8 + slot; n < NN; n += gridDim.x * 8) {
        float4 z = ((const float4*)(g_z2 + (size_t)n * HH))[q];
        float4 h;
        h.x = fmaxf(fmaf(z.x, scv[0], shv[0]), 0.f);
        h.y = fmaxf(fmaf(z.y, scv[1], shv[1]), 0.f);
        h.z = fmaxf(fmaf(z.z, scv[2], shv[2]), 0.f);
        h.w = fmaxf(fmaf(z.w, scv[3], shv[3]), 0.f);
        int b = __ldg(batch + n);
        red_add_v4(g_pooled + b * (LL * HH) + layer * HH + q * 4, h);
    }
}

// ---------------- head -------------------------------------------------------
__global__ void head_kernel(const float* __restrict__ fc1w,
                            const float* __restrict__ fc1b,
                            const float* __restrict__ fc2w,
                            const float* __restrict__ fc2b,
                            float* __restrict__ out) {
    __shared__ float p[LL * HH];
    __shared__ float tbuf[HH];
    const int g = blockIdx.x;
    const int j = threadIdx.x;
    for (int k = j; k < LL * HH; k += HH) p[k] = g_pooled[g * (LL * HH) + k];
    __syncthreads();
    float acc = __ldg(fc1b + j);
#pragma unroll 4
    for (int k = 0; k < LL * HH; k++) acc = fmaf(p[k], __ldg(fc1w + k * HH + j), acc);
    tbuf[j] = fmaxf(acc, 0.f);
    __syncthreads();
    if (j < CC) {
        float o = __ldg(fc2b + j);
#pragma unroll 4
        for (int k = 0; k < HH; k++) o = fmaf(tbuf[k], __ldg(fc2w + k * CC + j), o);
        out[g * CC + j] = o;
    }
}

// ---------------- launch -----------------------------------------------------
extern "C" void kernel_launch(void* const* d_in, const int* in_sizes, int n_in,
                              void* d_out, int out_size) {
    const float* x    = (const float*)d_in[0];
    const int*   ei   = (const int*)  d_in[1];
    const int*   batch= (const int*)  d_in[2];
    const float* W1   = (const float*)d_in[3];
    const float* b1   = (const float*)d_in[4];
    const float* g1   = (const float*)d_in[5];
    const float* bt1  = (const float*)d_in[6];
    const float* W2   = (const float*)d_in[7];
    const float* b2   = (const float*)d_in[8];
    const float* g2   = (const float*)d_in[9];
    const float* bt2  = (const float*)d_in[10];
    const float* eps  = (const float*)d_in[11];
    const float* fc1w = (const float*)d_in[12];
    const float* fc1b = (const float*)d_in[13];
    const float* fc2w = (const float*)d_in[14];
    const float* fc2b = (const float*)d_in[15];
    float* out = (float*)d_out;

    zero_kernel<<<180, 1024>>>();
    count_kernel<<<(EE + 255) / 256, 256>>>(ei);
    bsum_kernel<<<NBLK, 256>>>();
    bscan_kernel<<<1, 256>>>();
    rowptr_kernel<<<NBLK, 256>>>();
    fill_kernel<<<(EE + 255) / 256, 256>>>(ei);

    const int gemmBlocks = (NN + 127) / 128;  // 391
    for (int i = 0; i < LL; i++) {
        if (i == 0)
            agg_kernel<1><<<2048, 256>>>(x, eps, 0, batch,
                                         (const float*)0, (const float*)0);
        else
            agg_kernel<0><<<2048, 256>>>(x, eps, i, batch,
                                         g2 + (i - 1) * HH, bt2 + (i - 1) * HH);
        gemm_kernel<0><<<gemmBlocks, 256>>>(i, W1 + i * HH * HH, b1 + i * HH,
                                            (const float*)0, (const float*)0);
        gemm_kernel<1><<<gemmBlocks, 256>>>(i, W2 + i * HH * HH, b2 + i * HH,
                                            g1 + i * HH, bt1 + i * HH);
    }
    finalpool_kernel<<<2048, 256>>>(LL - 1, batch,
                                    g2 + (LL - 1) * HH, bt2 + (LL - 1) * HH);
    head_kernel<<<GG, HH>>>(fc1w, fc1b, fc2w, fc2b, out);
}